// round 6
// baseline (speedup 1.0000x reference)
#include <cuda_runtime.h>
#include <math.h>

// Problem constants
#define Bz 64
#define Oz 32
#define Iz 2048
#define Dz 16   // DOUT == DIN == 16

// ---------------- scratch (static device globals; no allocation) ----------------
__device__ float g_uhat[(size_t)Bz * Oz * Dz * Iz];   // 256 MiB, layout [b][o][d][i]
__device__ float g_d[(size_t)Bz * Oz * Iz];           // distances d[b][o][i]
__device__ float g_c[(size_t)Bz * Oz * Iz];           // routing coeffs (iter-1 scratch)
__device__ float g_partial[Bz * Oz];                  // per-CTA partial sums of d

#define WSTRIDE 260   // smem row stride in floats: 16B-aligned, conflict-free lane-per-i

// =======================================================================
// K1: u_hat[b,o,d,i] = clip( sum_k W[o,i,d,k] * u[b,i,k] )
// Grid: (I/32, O). Block: 256 = 32 i-lanes x 8 batch-groups.
// Each thread: 2 batches per pass, 4 passes. k-chunked float4 W reads
// (1 LDS.128 feeds 8 FFMA). Low regs -> 3+ CTAs/SM.
// =======================================================================
__global__ __launch_bounds__(256, 3) void k_uhat(const float* __restrict__ u,
                                                 const float* __restrict__ W)
{
    __shared__ float Wsm[32 * WSTRIDE];

    const int o  = blockIdx.y;
    const int i0 = blockIdx.x * 32;

    // Stage W[o, i0..i0+31, :, :] : contiguous 8192 floats
    const float* Wg = W + ((size_t)o * Iz + i0) * 256;
    for (int idx = threadIdx.x; idx < 8192; idx += 256) {
        int il = idx >> 8, j = idx & 255;
        Wsm[il * WSTRIDE + j] = Wg[idx];
    }
    __syncthreads();

    const int il = threadIdx.x & 31;
    const int bg = threadIdx.x >> 5;        // 0..7
    const int i  = i0 + il;
    const float* wrow = Wsm + il * WSTRIDE;

    for (int p = 0; p < 4; p++) {
        const int b0 = p * 16 + bg * 2;
        const int b1 = b0 + 1;

        float acc0[16], acc1[16];
        #pragma unroll
        for (int d = 0; d < 16; d++) { acc0[d] = 0.f; acc1[d] = 0.f; }
        float n2u0 = 0.f, n2u1 = 0.f;

        const float4* up0 = (const float4*)(u + ((size_t)b0 * Iz + i) * 16);
        const float4* up1 = (const float4*)(u + ((size_t)b1 * Iz + i) * 16);

        #pragma unroll
        for (int kc = 0; kc < 4; kc++) {
            float4 u0 = up0[kc];
            float4 u1 = up1[kc];
            n2u0 += u0.x*u0.x + u0.y*u0.y + u0.z*u0.z + u0.w*u0.w;
            n2u1 += u1.x*u1.x + u1.y*u1.y + u1.z*u1.z + u1.w*u1.w;
            #pragma unroll
            for (int d = 0; d < 16; d++) {
                float4 w = *(const float4*)(wrow + d * 16 + kc * 4);
                acc0[d] += w.x*u0.x + w.y*u0.y + w.z*u0.z + w.w*u0.w;
                acc1[d] += w.x*u1.x + w.y*u1.y + w.z*u1.z + w.w*u1.w;
            }
        }

        // norms + clip + store (2 batches)
        {
            float n2h = 0.f;
            #pragma unroll
            for (int d = 0; d < 16; d++) n2h += acc0[d] * acc0[d];
            float nh = sqrtf(n2h);
            float sc = fminf(nh, sqrtf(n2u0)) / (nh + 1e-12f);
            float* dst = g_uhat + (size_t)(b0 * Oz + o) * Dz * Iz + i;
            #pragma unroll
            for (int d = 0; d < 16; d++) dst[(size_t)d * Iz] = acc0[d] * sc;
        }
        {
            float n2h = 0.f;
            #pragma unroll
            for (int d = 0; d < 16; d++) n2h += acc1[d] * acc1[d];
            float nh = sqrtf(n2h);
            float sc = fminf(nh, sqrtf(n2u1)) / (nh + 1e-12f);
            float* dst = g_uhat + (size_t)(b1 * Oz + o) * Dz * Iz + i;
            #pragma unroll
            for (int d = 0; d < 16; d++) dst[(size_t)d * Iz] = acc1[d] * sc;
        }
    }
}

// =======================================================================
// k_sd: FUSED s/v + distance. Phase 1 reads u_hat from DRAM, phase 2
// re-reads it from L2 (slab is 128 KiB, just touched). Low regs, float4.
//   mode 0: c = 1/O uniform ; mode 1: c = g_c.
// Grid: (O, B). Block: 512 (each thread owns 4 consecutive i via float4).
// =======================================================================
__global__ __launch_bounds__(512, 2) void k_sd(int mode, const float* __restrict__ bias)
{
    const int o = blockIdx.x;
    const int b = blockIdx.y;
    const size_t base = (size_t)(b * Oz + o);
    const float4* uh4 = (const float4*)(g_uhat + base * Dz * Iz);
    const int t = threadIdx.x;

    // ---- phase 1: s accumulation ----
    float4 cc;
    if (mode == 0) cc = make_float4(1.f/32.f, 1.f/32.f, 1.f/32.f, 1.f/32.f);
    else           cc = ((const float4*)(g_c + base * Iz))[t];

    float acc[16];
    #pragma unroll
    for (int d = 0; d < 16; d++) {
        float4 x = uh4[d * 512 + t];
        acc[d] = cc.x*x.x + cc.y*x.y + cc.z*x.z + cc.w*x.w;
    }

    // reduce across 512 threads (16 warps)
    #pragma unroll
    for (int d = 0; d < 16; d++) {
        #pragma unroll
        for (int off = 16; off > 0; off >>= 1)
            acc[d] += __shfl_down_sync(0xffffffffu, acc[d], off);
    }

    __shared__ float red[16][16];
    __shared__ float vsm[16];
    const int lane = t & 31;
    const int wid  = t >> 5;
    if (lane == 0) {
        #pragma unroll
        for (int d = 0; d < 16; d++) red[wid][d] = acc[d];
    }
    __syncthreads();

    if (t < 16) {
        const int d = t;
        float tot = 0.f;
        #pragma unroll
        for (int w = 0; w < 16; w++) tot += red[w][d];
        float s = tot + bias[o * Dz + d];

        float n2 = s * s;
        #pragma unroll
        for (int off = 8; off > 0; off >>= 1)
            n2 += __shfl_xor_sync(0x0000ffffu, n2, off);

        vsm[d] = s * (n2 / ((1.0f + n2) * sqrtf(n2 + 1e-12f)));
    }
    __syncthreads();

    // ---- phase 2: distances (u_hat re-read hits L2) ----
    float4 s2 = make_float4(0.f, 0.f, 0.f, 0.f);
    #pragma unroll
    for (int d = 0; d < 16; d++) {
        float vd = vsm[d];
        float4 x = uh4[d * 512 + t];
        float dx = vd - x.x, dy = vd - x.y, dz = vd - x.z, dw = vd - x.w;
        s2.x += dx*dx; s2.y += dy*dy; s2.z += dz*dz; s2.w += dw*dw;
    }
    float4 dd = make_float4(sqrtf(s2.x), sqrtf(s2.y), sqrtf(s2.z), sqrtf(s2.w));
    ((float4*)(g_d + base * Iz))[t] = dd;

    float lsum = (dd.x + dd.y) + (dd.z + dd.w);
    #pragma unroll
    for (int off = 16; off > 0; off >>= 1)
        lsum += __shfl_down_sync(0xffffffffu, lsum, off);

    __shared__ float red1[16];
    if (lane == 0) red1[wid] = lsum;
    __syncthreads();
    if (t == 0) {
        float tt = 0.f;
        #pragma unroll
        for (int w = 0; w < 16; w++) tt += red1[w];
        g_partial[base] = tt;
    }
}

// =======================================================================
// k_c: computes t from g_partial (deterministic fixed-order, identical in
// every block), then c[b,o,i] = softmax over o of (t * d[b,o,i]).
// cout == nullptr -> write g_c, else write cout (final output region).
// =======================================================================
__global__ __launch_bounds__(256, 1) void k_c(float* __restrict__ cout)
{
    __shared__ float psum[256];
    __shared__ float tsh;
    {
        float s = 0.f;
        const int j0 = threadIdx.x * 8;
        #pragma unroll
        for (int j = 0; j < 8; j++) s += g_partial[j0 + j];
        psum[threadIdx.x] = s;
    }
    __syncthreads();
    if (threadIdx.x == 0) {
        float tot = 0.f;
        for (int w = 0; w < 256; w++) tot += psum[w];
        float mean = tot / (float)((size_t)Bz * Oz * Iz);
        const float t_const = 5.6312118f;   // ln(279)
        tsh = t_const / (1e-12f - 0.5f * mean);
    }
    __syncthreads();
    const float t = tsh;

    const int idx = blockIdx.x * 256 + threadIdx.x;
    const int b = idx >> 11;
    const int i = idx & (Iz - 1);

    float vals[32];
    float mx = -1e30f;
    #pragma unroll
    for (int o = 0; o < 32; o++) {
        float x = t * g_d[(size_t)(b * Oz + o) * Iz + i];
        vals[o] = x;
        mx = fmaxf(mx, x);
    }
    float ssum = 0.f;
    #pragma unroll
    for (int o = 0; o < 32; o++) {
        float e = expf(vals[o] - mx);
        vals[o] = e;
        ssum += e;
    }
    float inv = 1.0f / ssum;
    float* dst = cout ? cout : g_c;
    #pragma unroll
    for (int o = 0; o < 32; o++)
        dst[(size_t)(b * Oz + o) * Iz + i] = vals[o] * inv;
}

// =======================================================================
// k_s_final: final s/v with c read from the output buffer; writes v to out.
// Grid: (O, B). Block: 512, float4 over i.
// =======================================================================
__global__ __launch_bounds__(512, 2) void k_s_final(const float* __restrict__ cext,
                                                    const float* __restrict__ bias,
                                                    float* __restrict__ vext)
{
    const int o = blockIdx.x;
    const int b = blockIdx.y;
    const size_t base = (size_t)(b * Oz + o);
    const float4* uh4 = (const float4*)(g_uhat + base * Dz * Iz);
    const int t = threadIdx.x;

    float4 cc = ((const float4*)(cext + base * Iz))[t];

    float acc[16];
    #pragma unroll
    for (int d = 0; d < 16; d++) {
        float4 x = uh4[d * 512 + t];
        acc[d] = cc.x*x.x + cc.y*x.y + cc.z*x.z + cc.w*x.w;
    }

    #pragma unroll
    for (int d = 0; d < 16; d++) {
        #pragma unroll
        for (int off = 16; off > 0; off >>= 1)
            acc[d] += __shfl_down_sync(0xffffffffu, acc[d], off);
    }

    __shared__ float red[16][16];
    const int lane = t & 31;
    const int wid  = t >> 5;
    if (lane == 0) {
        #pragma unroll
        for (int d = 0; d < 16; d++) red[wid][d] = acc[d];
    }
    __syncthreads();

    if (t < 16) {
        const int d = t;
        float tot = 0.f;
        #pragma unroll
        for (int w = 0; w < 16; w++) tot += red[w][d];
        float s = tot + bias[o * Dz + d];

        float n2 = s * s;
        #pragma unroll
        for (int off = 8; off > 0; off >>= 1)
            n2 += __shfl_xor_sync(0x0000ffffu, n2, off);

        vext[(b * Oz + o) * Dz + d] = s * (n2 / ((1.0f + n2) * sqrtf(n2 + 1e-12f)));
    }
}

// =======================================================================
extern "C" void kernel_launch(void* const* d_in, const int* in_sizes, int n_in,
                              void* d_out, int out_size)
{
    const float* u    = (const float*)d_in[0];   // [64, 2048, 16]
    const float* W    = (const float*)d_in[1];   // [1, 32, 2048, 16, 16]
    const float* bias = (const float*)d_in[2];   // [1, 32, 16]

    float* out        = (float*)d_out;
    float* vout_final = out;                     // [64,32,16]
    float* cout_final = out + Bz * Oz * Dz;      // [64,32,2048,1]

    dim3 gUH(Iz / 32, Oz);
    dim3 gBO(Oz, Bz);

    k_uhat<<<gUH, 256>>>(u, W);

    // iteration 0: c uniform; fused s/v + d
    k_sd<<<gBO, 512>>>(0, bias);

    // iteration 1
    k_c<<<(Bz * Iz) / 256, 256>>>(nullptr);      // t + softmax -> g_c
    k_sd<<<gBO, 512>>>(1, bias);

    // iteration 2 (final): c2 and v2 go straight to d_out
    k_c<<<(Bz * Iz) / 256, 256>>>(cout_final);   // t + softmax -> out
    k_s_final<<<gBO, 512>>>(cout_final, bias, vout_final);
}

// round 7
// speedup vs baseline: 1.4782x; 1.4782x over previous
#include <cuda_runtime.h>
#include <math.h>

// Problem constants
#define Bz 64
#define Oz 32
#define Iz 2048
#define Dz 16   // DOUT == DIN == 16

// ---------------- scratch (static device globals; no allocation) ----------------
__device__ float g_uhat[(size_t)Bz * Oz * Dz * Iz];   // 256 MiB, layout [b][o][d][i]
__device__ float g_d[(size_t)Bz * Oz * Iz];           // distances d[b][o][i]
__device__ float g_c[(size_t)Bz * Oz * Iz];           // routing coeffs (iter-1 scratch)
__device__ float g_partial[Bz * Oz];                  // per-CTA partial sums of d

#define WSTRIDE 260   // smem row stride in floats: 16B-aligned; float4 reads are
                      // phase-conflict-free (quad-group = lane%8 + const)

// =======================================================================
// K1: u_hat[b,o,d,i] = clip( sum_k W[o,i,d,k] * u[b,i,k] )
// Grid: (I/32, O). Block: 256 = 32 i-lanes x 8 batch-groups.
// Each thread: 2 batches per pass, 4 passes; float4 LDS (1 LDS.128 : 8 FFMA).
// NO min-blocks launch bound: letting regs float (~80) avoids local spills;
// RF still admits 3 CTAs/SM.
// =======================================================================
__global__ __launch_bounds__(256) void k_uhat(const float* __restrict__ u,
                                              const float* __restrict__ W)
{
    __shared__ float Wsm[32 * WSTRIDE];

    const int o  = blockIdx.y;
    const int i0 = blockIdx.x * 32;

    // Stage W[o, i0..i0+31, :, :] : contiguous 8192 floats
    const float* Wg = W + ((size_t)o * Iz + i0) * 256;
    for (int idx = threadIdx.x; idx < 8192; idx += 256) {
        int il = idx >> 8, j = idx & 255;
        Wsm[il * WSTRIDE + j] = Wg[idx];
    }
    __syncthreads();

    const int il = threadIdx.x & 31;
    const int bg = threadIdx.x >> 5;        // 0..7
    const int i  = i0 + il;
    const float* wrow = Wsm + il * WSTRIDE;

    for (int p = 0; p < 4; p++) {
        const int b0 = p * 16 + bg * 2;
        const int b1 = b0 + 1;

        float acc0[16], acc1[16];
        #pragma unroll
        for (int d = 0; d < 16; d++) { acc0[d] = 0.f; acc1[d] = 0.f; }
        float n2u0 = 0.f, n2u1 = 0.f;

        const float4* up0 = (const float4*)(u + ((size_t)b0 * Iz + i) * 16);
        const float4* up1 = (const float4*)(u + ((size_t)b1 * Iz + i) * 16);

        #pragma unroll
        for (int kc = 0; kc < 4; kc++) {
            float4 u0 = up0[kc];
            float4 u1 = up1[kc];
            n2u0 += u0.x*u0.x + u0.y*u0.y + u0.z*u0.z + u0.w*u0.w;
            n2u1 += u1.x*u1.x + u1.y*u1.y + u1.z*u1.z + u1.w*u1.w;
            #pragma unroll
            for (int d = 0; d < 16; d++) {
                float4 w = *(const float4*)(wrow + d * 16 + kc * 4);
                acc0[d] += w.x*u0.x + w.y*u0.y + w.z*u0.z + w.w*u0.w;
                acc1[d] += w.x*u1.x + w.y*u1.y + w.z*u1.z + w.w*u1.w;
            }
        }

        // norms + clip + store (2 batches)
        {
            float n2h = 0.f;
            #pragma unroll
            for (int d = 0; d < 16; d++) n2h += acc0[d] * acc0[d];
            float nh = sqrtf(n2h);
            float sc = fminf(nh, sqrtf(n2u0)) / (nh + 1e-12f);
            float* dst = g_uhat + (size_t)(b0 * Oz + o) * Dz * Iz + i;
            #pragma unroll
            for (int d = 0; d < 16; d++) dst[(size_t)d * Iz] = acc0[d] * sc;
        }
        {
            float n2h = 0.f;
            #pragma unroll
            for (int d = 0; d < 16; d++) n2h += acc1[d] * acc1[d];
            float nh = sqrtf(n2h);
            float sc = fminf(nh, sqrtf(n2u1)) / (nh + 1e-12f);
            float* dst = g_uhat + (size_t)(b1 * Oz + o) * Dz * Iz + i;
            #pragma unroll
            for (int d = 0; d < 16; d++) dst[(size_t)d * Iz] = acc1[d] * sc;
        }
    }
}

// =======================================================================
// k_sd: FUSED s/v + distance. Phase 1 reads u_hat from DRAM, phase 2
// re-reads it from L2 (slab is 128 KiB, just touched). Low regs, float4.
//   mode 0: c = 1/O uniform ; mode 1: c = g_c.
// Grid: (O, B). Block: 512 (each thread owns 4 consecutive i via float4).
// =======================================================================
__global__ __launch_bounds__(512, 2) void k_sd(int mode, const float* __restrict__ bias)
{
    const int o = blockIdx.x;
    const int b = blockIdx.y;
    const size_t base = (size_t)(b * Oz + o);
    const float4* uh4 = (const float4*)(g_uhat + base * Dz * Iz);
    const int t = threadIdx.x;

    // ---- phase 1: s accumulation ----
    float4 cc;
    if (mode == 0) cc = make_float4(1.f/32.f, 1.f/32.f, 1.f/32.f, 1.f/32.f);
    else           cc = ((const float4*)(g_c + base * Iz))[t];

    float acc[16];
    #pragma unroll
    for (int d = 0; d < 16; d++) {
        float4 x = uh4[d * 512 + t];
        acc[d] = cc.x*x.x + cc.y*x.y + cc.z*x.z + cc.w*x.w;
    }

    // reduce across 512 threads (16 warps)
    #pragma unroll
    for (int d = 0; d < 16; d++) {
        #pragma unroll
        for (int off = 16; off > 0; off >>= 1)
            acc[d] += __shfl_down_sync(0xffffffffu, acc[d], off);
    }

    __shared__ float red[16][16];
    __shared__ float vsm[16];
    const int lane = t & 31;
    const int wid  = t >> 5;
    if (lane == 0) {
        #pragma unroll
        for (int d = 0; d < 16; d++) red[wid][d] = acc[d];
    }
    __syncthreads();

    if (t < 16) {
        const int d = t;
        float tot = 0.f;
        #pragma unroll
        for (int w = 0; w < 16; w++) tot += red[w][d];
        float s = tot + bias[o * Dz + d];

        float n2 = s * s;
        #pragma unroll
        for (int off = 8; off > 0; off >>= 1)
            n2 += __shfl_xor_sync(0x0000ffffu, n2, off);

        vsm[d] = s * (n2 / ((1.0f + n2) * sqrtf(n2 + 1e-12f)));
    }
    __syncthreads();

    // ---- phase 2: distances (u_hat re-read hits L2) ----
    float4 s2 = make_float4(0.f, 0.f, 0.f, 0.f);
    #pragma unroll
    for (int d = 0; d < 16; d++) {
        float vd = vsm[d];
        float4 x = uh4[d * 512 + t];
        float dx = vd - x.x, dy = vd - x.y, dz = vd - x.z, dw = vd - x.w;
        s2.x += dx*dx; s2.y += dy*dy; s2.z += dz*dz; s2.w += dw*dw;
    }
    float4 dd = make_float4(sqrtf(s2.x), sqrtf(s2.y), sqrtf(s2.z), sqrtf(s2.w));
    ((float4*)(g_d + base * Iz))[t] = dd;

    float lsum = (dd.x + dd.y) + (dd.z + dd.w);
    #pragma unroll
    for (int off = 16; off > 0; off >>= 1)
        lsum += __shfl_down_sync(0xffffffffu, lsum, off);

    __shared__ float red1[16];
    if (lane == 0) red1[wid] = lsum;
    __syncthreads();
    if (t == 0) {
        float tt = 0.f;
        #pragma unroll
        for (int w = 0; w < 16; w++) tt += red1[w];
        g_partial[base] = tt;
    }
}

// =======================================================================
// k_c: computes t from g_partial (deterministic fixed-order, identical in
// every block), then c[b,o,i] = softmax over o of (t * d[b,o,i]).
// cout == nullptr -> write g_c, else write cout (final output region).
// =======================================================================
__global__ __launch_bounds__(256, 1) void k_c(float* __restrict__ cout)
{
    __shared__ float psum[256];
    __shared__ float tsh;
    {
        float s = 0.f;
        const int j0 = threadIdx.x * 8;
        #pragma unroll
        for (int j = 0; j < 8; j++) s += g_partial[j0 + j];
        psum[threadIdx.x] = s;
    }
    __syncthreads();
    if (threadIdx.x == 0) {
        float tot = 0.f;
        for (int w = 0; w < 256; w++) tot += psum[w];
        float mean = tot / (float)((size_t)Bz * Oz * Iz);
        const float t_const = 5.6312118f;   // ln(279)
        tsh = t_const / (1e-12f - 0.5f * mean);
    }
    __syncthreads();
    const float t = tsh;

    const int idx = blockIdx.x * 256 + threadIdx.x;
    const int b = idx >> 11;
    const int i = idx & (Iz - 1);

    float vals[32];
    float mx = -1e30f;
    #pragma unroll
    for (int o = 0; o < 32; o++) {
        float x = t * g_d[(size_t)(b * Oz + o) * Iz + i];
        vals[o] = x;
        mx = fmaxf(mx, x);
    }
    float ssum = 0.f;
    #pragma unroll
    for (int o = 0; o < 32; o++) {
        float e = expf(vals[o] - mx);
        vals[o] = e;
        ssum += e;
    }
    float inv = 1.0f / ssum;
    float* dst = cout ? cout : g_c;
    #pragma unroll
    for (int o = 0; o < 32; o++)
        dst[(size_t)(b * Oz + o) * Iz + i] = vals[o] * inv;
}

// =======================================================================
// k_s_final: final s/v with c read from the output buffer; writes v to out.
// Grid: (O, B). Block: 512, float4 over i.
// =======================================================================
__global__ __launch_bounds__(512, 2) void k_s_final(const float* __restrict__ cext,
                                                    const float* __restrict__ bias,
                                                    float* __restrict__ vext)
{
    const int o = blockIdx.x;
    const int b = blockIdx.y;
    const size_t base = (size_t)(b * Oz + o);
    const float4* uh4 = (const float4*)(g_uhat + base * Dz * Iz);
    const int t = threadIdx.x;

    float4 cc = ((const float4*)(cext + base * Iz))[t];

    float acc[16];
    #pragma unroll
    for (int d = 0; d < 16; d++) {
        float4 x = uh4[d * 512 + t];
        acc[d] = cc.x*x.x + cc.y*x.y + cc.z*x.z + cc.w*x.w;
    }

    #pragma unroll
    for (int d = 0; d < 16; d++) {
        #pragma unroll
        for (int off = 16; off > 0; off >>= 1)
            acc[d] += __shfl_down_sync(0xffffffffu, acc[d], off);
    }

    __shared__ float red[16][16];
    const int lane = t & 31;
    const int wid  = t >> 5;
    if (lane == 0) {
        #pragma unroll
        for (int d = 0; d < 16; d++) red[wid][d] = acc[d];
    }
    __syncthreads();

    if (t < 16) {
        const int d = t;
        float tot = 0.f;
        #pragma unroll
        for (int w = 0; w < 16; w++) tot += red[w][d];
        float s = tot + bias[o * Dz + d];

        float n2 = s * s;
        #pragma unroll
        for (int off = 8; off > 0; off >>= 1)
            n2 += __shfl_xor_sync(0x0000ffffu, n2, off);

        vext[(b * Oz + o) * Dz + d] = s * (n2 / ((1.0f + n2) * sqrtf(n2 + 1e-12f)));
    }
}

// =======================================================================
extern "C" void kernel_launch(void* const* d_in, const int* in_sizes, int n_in,
                              void* d_out, int out_size)
{
    const float* u    = (const float*)d_in[0];   // [64, 2048, 16]
    const float* W    = (const float*)d_in[1];   // [1, 32, 2048, 16, 16]
    const float* bias = (const float*)d_in[2];   // [1, 32, 16]

    float* out        = (float*)d_out;
    float* vout_final = out;                     // [64,32,16]
    float* cout_final = out + Bz * Oz * Dz;      // [64,32,2048,1]

    dim3 gUH(Iz / 32, Oz);
    dim3 gBO(Oz, Bz);

    k_uhat<<<gUH, 256>>>(u, W);

    // iteration 0: c uniform; fused s/v + d
    k_sd<<<gBO, 512>>>(0, bias);

    // iteration 1
    k_c<<<(Bz * Iz) / 256, 256>>>(nullptr);      // t + softmax -> g_c
    k_sd<<<gBO, 512>>>(1, bias);

    // iteration 2 (final): c2 and v2 go straight to d_out
    k_c<<<(Bz * Iz) / 256, 256>>>(cout_final);   // t + softmax -> out
    k_s_final<<<gBO, 512>>>(cout_final, bias, vout_final);
}

// round 10
// speedup vs baseline: 2.4352x; 1.6474x over previous
#include <cuda_runtime.h>
#include <math.h>

// Problem constants
#define Bz 64
#define Oz 32
#define Iz 2048
#define Dz 16   // DOUT == DIN == 16

// ---------------- scratch (static device globals; no allocation) ----------------
__device__ float g_uhat[(size_t)Bz * Oz * Dz * Iz];   // 256 MiB, layout [b][o][d][i]
__device__ float g_d[(size_t)Bz * Oz * Iz];           // distances d[b][o][i]
__device__ float g_c[(size_t)Bz * Oz * Iz];           // routing coeffs (iter-1 scratch)
__device__ float g_partial[Bz * Oz];                  // per-CTA partial sums of d
__device__ float g_unorm[(size_t)Bz * Iz];            // ||u[b,i]|| (precomputed)

// =======================================================================
// k_unorm: ||u[b,i]|| for all (b,i). 128K threads, trivially coalesced.
// =======================================================================
__global__ __launch_bounds__(256) void k_unorm(const float* __restrict__ u)
{
    const int idx = blockIdx.x * 256 + threadIdx.x;   // b*Iz + i
    const float4* up = (const float4*)(u + (size_t)idx * 16);
    float n2 = 0.f;
    #pragma unroll
    for (int q = 0; q < 4; q++) {
        float4 t = up[q];
        n2 += t.x*t.x + t.y*t.y + t.z*t.z + t.w*t.w;
    }
    g_unorm[idx] = sqrtf(n2);
}

// =======================================================================
// K1: u_hat[b,o,d,i] = clip( sum_k W[o,i,d,k] * u[b,i,k] )
// Grid: (I/32, O). Block: 256 = 8 warps; lane = il_local*8 + dg.
//   warp w covers i = i0 + 4w .. i0+4w+3 (il_local 0..3), dg = 2-row d-group.
// W rows for this thread's 2 d's live in REGISTERS (32 floats, loaded once).
// u staged to smem in 16-batch chunks; inner LDS.128 are 8-lane broadcasts.
// Norm over d reduced with 3 shfl_xor inside the 8-lane dg group.
// Tiny per-thread state -> high occupancy, no spills.
// =======================================================================
__global__ __launch_bounds__(256) void k_uhat(const float* __restrict__ u,
                                              const float* __restrict__ W)
{
    __shared__ float pool[32 * 264];        // 33.8 KB: W staging, then u chunks
    __shared__ float un_sm[512];            // ||u|| for current chunk (16b x 32i)

    const int o  = blockIdx.y;
    const int i0 = blockIdx.x * 32;
    const int tid  = threadIdx.x;
    const int w    = tid >> 5;
    const int lane = tid & 31;
    const int il_l = lane >> 3;             // 0..3
    const int dg   = lane & 7;              // 0..7 -> d rows 2dg, 2dg+1
    const int il   = w * 4 + il_l;          // 0..31
    const int i    = i0 + il;

    // ---- stage W[o, i0..i0+31, :, :] (8192 contiguous floats), coalesced ----
    const float* Wg = W + ((size_t)o * Iz + i0) * 256;
    for (int idx = tid; idx < 8192; idx += 256) {
        int ils = idx >> 8, j = idx & 255;
        pool[ils * 264 + j] = Wg[idx];
    }
    __syncthreads();

    // ---- pull this thread's 2 W rows into registers ----
    float wA[16], wB[16];
    {
        const float* r0 = &pool[il * 264 + (2 * dg) * 16];
        const float* r1 = r0 + 16;
        #pragma unroll
        for (int q = 0; q < 4; q++) {
            float4 a = *(const float4*)(r0 + q * 4);
            float4 b = *(const float4*)(r1 + q * 4);
            wA[q*4+0] = a.x; wA[q*4+1] = a.y; wA[q*4+2] = a.z; wA[q*4+3] = a.w;
            wB[q*4+0] = b.x; wB[q*4+1] = b.y; wB[q*4+2] = b.z; wB[q*4+3] = b.w;
        }
    }
    __syncthreads();   // everyone done reading W before u overwrites pool

    // ---- 4 chunks of 16 batches ----
    for (int bc = 0; bc < 4; bc++) {
        // stage u[bc*16 .. bc*16+15][i0..i0+31][:] : 16 x 512 contiguous floats
        const float* ug = u + ((size_t)(bc * 16) * Iz + i0) * 16;
        for (int idx = tid; idx < 8192; idx += 256) {
            int bl = idx >> 9, r = idx & 511;
            pool[bl * 512 + r] = ug[(size_t)bl * Iz * 16 + r];
        }
        // stage ||u|| for this chunk (512 entries, 256 threads -> 2 per thread)
        for (int idx = tid; idx < 512; idx += 256) {
            int bl = idx >> 5, ii = idx & 31;
            un_sm[idx] = g_unorm[(size_t)(bc * 16 + bl) * Iz + i0 + ii];
        }
        __syncthreads();

        #pragma unroll 4
        for (int bl = 0; bl < 16; bl++) {
            const float* ub = &pool[bl * 512 + il * 16];   // broadcast reads
            float4 u0 = *(const float4*)(ub + 0);
            float4 u1 = *(const float4*)(ub + 4);
            float4 u2 = *(const float4*)(ub + 8);
            float4 u3 = *(const float4*)(ub + 12);
            float uu[16] = {u0.x,u0.y,u0.z,u0.w, u1.x,u1.y,u1.z,u1.w,
                            u2.x,u2.y,u2.z,u2.w, u3.x,u3.y,u3.z,u3.w};

            float a0 = 0.f, a1 = 0.f;
            #pragma unroll
            for (int k = 0; k < 16; k++) {
                a0 += wA[k] * uu[k];
                a1 += wB[k] * uu[k];
            }

            // ||u_hat||^2 over all 16 d: reduce across the 8 dg lanes
            float n2 = a0 * a0 + a1 * a1;
            n2 += __shfl_xor_sync(0xffffffffu, n2, 1);
            n2 += __shfl_xor_sync(0xffffffffu, n2, 2);
            n2 += __shfl_xor_sync(0xffffffffu, n2, 4);

            float nh = sqrtf(n2);
            float nu = un_sm[bl * 32 + il];
            float sc = fminf(nh, nu) / (nh + 1e-12f);

            const int b = bc * 16 + bl;
            float* dst = g_uhat + ((size_t)(b * Oz + o) * Dz + 2 * dg) * Iz + i;
            dst[0]  = a0 * sc;
            dst[Iz] = a1 * sc;
        }
        __syncthreads();   // before next chunk overwrites pool
    }
}

// =======================================================================
// k_sd: FUSED s/v + distance. Phase 1 reads u_hat from DRAM, phase 2
// re-reads it from L2 (slab is 128 KiB, just touched). Low regs, float4.
//   mode 0: c = 1/O uniform ; mode 1: c = g_c.
// Grid: (O, B). Block: 512 (each thread owns 4 consecutive i via float4).
// =======================================================================
__global__ __launch_bounds__(512, 2) void k_sd(int mode, const float* __restrict__ bias)
{
    const int o = blockIdx.x;
    const int b = blockIdx.y;
    const size_t base = (size_t)(b * Oz + o);
    const float4* uh4 = (const float4*)(g_uhat + base * Dz * Iz);
    const int t = threadIdx.x;

    // ---- phase 1: s accumulation ----
    float4 cc;
    if (mode == 0) cc = make_float4(1.f/32.f, 1.f/32.f, 1.f/32.f, 1.f/32.f);
    else           cc = ((const float4*)(g_c + base * Iz))[t];

    float acc[16];
    #pragma unroll
    for (int d = 0; d < 16; d++) {
        float4 x = uh4[d * 512 + t];
        acc[d] = cc.x*x.x + cc.y*x.y + cc.z*x.z + cc.w*x.w;
    }

    // reduce across 512 threads (16 warps)
    #pragma unroll
    for (int d = 0; d < 16; d++) {
        #pragma unroll
        for (int off = 16; off > 0; off >>= 1)
            acc[d] += __shfl_down_sync(0xffffffffu, acc[d], off);
    }

    __shared__ float red[16][16];
    __shared__ float vsm[16];
    const int lane = t & 31;
    const int wid  = t >> 5;
    if (lane == 0) {
        #pragma unroll
        for (int d = 0; d < 16; d++) red[wid][d] = acc[d];
    }
    __syncthreads();

    if (t < 16) {
        const int d = t;
        float tot = 0.f;
        #pragma unroll
        for (int w = 0; w < 16; w++) tot += red[w][d];
        float s = tot + bias[o * Dz + d];

        float n2 = s * s;
        #pragma unroll
        for (int off = 8; off > 0; off >>= 1)
            n2 += __shfl_xor_sync(0x0000ffffu, n2, off);

        vsm[d] = s * (n2 / ((1.0f + n2) * sqrtf(n2 + 1e-12f)));
    }
    __syncthreads();

    // ---- phase 2: distances (u_hat re-read hits L2) ----
    float4 s2 = make_float4(0.f, 0.f, 0.f, 0.f);
    #pragma unroll
    for (int d = 0; d < 16; d++) {
        float vd = vsm[d];
        float4 x = uh4[d * 512 + t];
        float dx = vd - x.x, dy = vd - x.y, dz = vd - x.z, dw = vd - x.w;
        s2.x += dx*dx; s2.y += dy*dy; s2.z += dz*dz; s2.w += dw*dw;
    }
    float4 dd = make_float4(sqrtf(s2.x), sqrtf(s2.y), sqrtf(s2.z), sqrtf(s2.w));
    ((float4*)(g_d + base * Iz))[t] = dd;

    float lsum = (dd.x + dd.y) + (dd.z + dd.w);
    #pragma unroll
    for (int off = 16; off > 0; off >>= 1)
        lsum += __shfl_down_sync(0xffffffffu, lsum, off);

    __shared__ float red1[16];
    if (lane == 0) red1[wid] = lsum;
    __syncthreads();
    if (t == 0) {
        float tt = 0.f;
        #pragma unroll
        for (int w = 0; w < 16; w++) tt += red1[w];
        g_partial[base] = tt;
    }
}

// =======================================================================
// k_c: computes t from g_partial (deterministic fixed-order, identical in
// every block), then c[b,o,i] = softmax over o of (t * d[b,o,i]).
// cout == nullptr -> write g_c, else write cout (final output region).
// =======================================================================
__global__ __launch_bounds__(256, 1) void k_c(float* __restrict__ cout)
{
    __shared__ float psum[256];
    __shared__ float tsh;
    {
        float s = 0.f;
        const int j0 = threadIdx.x * 8;
        #pragma unroll
        for (int j = 0; j < 8; j++) s += g_partial[j0 + j];
        psum[threadIdx.x] = s;
    }
    __syncthreads();
    if (threadIdx.x == 0) {
        float tot = 0.f;
        for (int w = 0; w < 256; w++) tot += psum[w];
        float mean = tot / (float)((size_t)Bz * Oz * Iz);
        const float t_const = 5.6312118f;   // ln(279)
        tsh = t_const / (1e-12f - 0.5f * mean);
    }
    __syncthreads();
    const float t = tsh;

    const int idx = blockIdx.x * 256 + threadIdx.x;
    const int b = idx >> 11;
    const int i = idx & (Iz - 1);

    float vals[32];
    float mx = -1e30f;
    #pragma unroll
    for (int o = 0; o < 32; o++) {
        float x = t * g_d[(size_t)(b * Oz + o) * Iz + i];
        vals[o] = x;
        mx = fmaxf(mx, x);
    }
    float ssum = 0.f;
    #pragma unroll
    for (int o = 0; o < 32; o++) {
        float e = expf(vals[o] - mx);
        vals[o] = e;
        ssum += e;
    }
    float inv = 1.0f / ssum;
    float* dst = cout ? cout : g_c;
    #pragma unroll
    for (int o = 0; o < 32; o++)
        dst[(size_t)(b * Oz + o) * Iz + i] = vals[o] * inv;
}

// =======================================================================
// k_s_final: final s/v with c read from the output buffer; writes v to out.
// Grid: (O, B). Block: 512, float4 over i.
// =======================================================================
__global__ __launch_bounds__(512, 2) void k_s_final(const float* __restrict__ cext,
                                                    const float* __restrict__ bias,
                                                    float* __restrict__ vext)
{
    const int o = blockIdx.x;
    const int b = blockIdx.y;
    const size_t base = (size_t)(b * Oz + o);
    const float4* uh4 = (const float4*)(g_uhat + base * Dz * Iz);
    const int t = threadIdx.x;

    float4 cc = ((const float4*)(cext + base * Iz))[t];

    float acc[16];
    #pragma unroll
    for (int d = 0; d < 16; d++) {
        float4 x = uh4[d * 512 + t];
        acc[d] = cc.x*x.x + cc.y*x.y + cc.z*x.z + cc.w*x.w;
    }

    #pragma unroll
    for (int d = 0; d < 16; d++) {
        #pragma unroll
        for (int off = 16; off > 0; off >>= 1)
            acc[d] += __shfl_down_sync(0xffffffffu, acc[d], off);
    }

    __shared__ float red[16][16];
    const int lane = t & 31;
    const int wid  = t >> 5;
    if (lane == 0) {
        #pragma unroll
        for (int d = 0; d < 16; d++) red[wid][d] = acc[d];
    }
    __syncthreads();

    if (t < 16) {
        const int d = t;
        float tot = 0.f;
        #pragma unroll
        for (int w = 0; w < 16; w++) tot += red[w][d];
        float s = tot + bias[o * Dz + d];

        float n2 = s * s;
        #pragma unroll
        for (int off = 8; off > 0; off >>= 1)
            n2 += __shfl_xor_sync(0x0000ffffu, n2, off);

        vext[(b * Oz + o) * Dz + d] = s * (n2 / ((1.0f + n2) * sqrtf(n2 + 1e-12f)));
    }
}

// =======================================================================
extern "C" void kernel_launch(void* const* d_in, const int* in_sizes, int n_in,
                              void* d_out, int out_size)
{
    const float* u    = (const float*)d_in[0];   // [64, 2048, 16]
    const float* W    = (const float*)d_in[1];   // [1, 32, 2048, 16, 16]
    const float* bias = (const float*)d_in[2];   // [1, 32, 16]

    float* out        = (float*)d_out;
    float* vout_final = out;                     // [64,32,16]
    float* cout_final = out + Bz * Oz * Dz;      // [64,32,2048,1]

    dim3 gUH(Iz / 32, Oz);
    dim3 gBO(Oz, Bz);

    k_unorm<<<(Bz * Iz) / 256, 256>>>(u);
    k_uhat<<<gUH, 256>>>(u, W);

    // iteration 0: c uniform; fused s/v + d
    k_sd<<<gBO, 512>>>(0, bias);

    // iteration 1
    k_c<<<(Bz * Iz) / 256, 256>>>(nullptr);      // t + softmax -> g_c
    k_sd<<<gBO, 512>>>(1, bias);

    // iteration 2 (final): c2 and v2 go straight to d_out
    k_c<<<(Bz * Iz) / 256, 256>>>(cout_final);   // t + softmax -> out
    k_s_final<<<gBO, 512>>>(cout_final, bias, vout_final);
}